// round 11
// baseline (speedup 1.0000x reference)
#include <cuda_runtime.h>

// Problem constants
#define BB 32
#define FF 64
#define LL 8192
#define KK 8
#define TT 128          // output steps per chunk
#define WW 128          // warm-up steps (validated rounds 2-9: rel_err ~1e-7)
#define NCH (LL / TT)   // 64 chunks -> 2048 blocks = one wave at 14/SM
#define TILE 16         // steps per staged tile (64 rows x 16 floats, packed)
#define XS_N (WW + TT + KK)   // 264

#define X_SCALE 20.0f
#define THR 0.25f
#define BETA 15.0f

// Packed XOR-swizzled tile: offset(row, slot) = row*16 + (slot ^ ((row>>1)&3))*4
// (slot = float4 column 0..3). Conflict-free for staging STS.128 (row=f, fixed
// slot), write-out LDS.128 (2 rows x 4 slots per 8-lane phase), and logits
// scalar LDS (odd groups walk rows in order i^1 so the two half-warps use
// disjoint bank halves).

// Fused conv + LIF scan + logits. Grid (B, NCH), 64 threads (one per filter).
// s derived from z at write-out (s = z>=0, z = BETA*(vpre-THR)).
__global__ __launch_bounds__(64, 14) void snn_fused_kernel(
    const float* __restrict__ x,
    const float* __restrict__ conv_w,
    const float* __restrict__ raw_tau,
    float* __restrict__ out)
{
    __shared__ float xs[XS_N];
    __shared__ float tI[FF * TILE];   // 4 KB packed
    __shared__ float tZ[FF * TILE];   // 4 KB packed
    __shared__ float pm[TILE * 4];    // 4 groups x 16 cols partial maxes

    const int b = blockIdx.x;
    const int c = blockIdx.y;
    const int f = threadIdx.x;
    const int t0 = c * TT;
    const int tstart = (c == 0) ? 0 : (t0 - WW);
    const int nwarm = t0 - tstart;    // 0 or WW

    // Unit-norm filter weights (clamp 1e-8)
    float w[KK];
    float nrm = 0.0f;
#pragma unroll
    for (int k = 0; k < KK; k++) {
        w[k] = conv_w[f * KK + k];
        nrm += w[k] * w[k];
    }
    nrm = fmaxf(sqrtf(nrm), 1e-8f);
#pragma unroll
    for (int k = 0; k < KK; k++) w[k] = w[k] / nrm;

    // alpha = exp(-1 / (softplus(raw_tau) + 1e-4))
    const float rt = raw_tau[f];
    const float sp = fmaxf(rt, 0.0f) + log1pf(expf(-fabsf(rt)));
    const float alpha = expf(-1.0f / (sp + 1e-4f));
    const float oma = 1.0f - alpha;

    // Stage pre-scaled x window, zero-padded left. xs[i] = 20*x[b, tstart-7+i]
    const float* xb = x + b * LL;
    const int base = tstart - (KK - 1);
    const int total = nwarm + TT + (KK - 1);
    for (int i = f; i < total; i += FF) {
        const int g = base + i;
        xs[i] = (g >= 0) ? (X_SCALE * xb[g]) : 0.0f;
    }
    __syncthreads();

    // 8-register circular window: win[(p+k)&7] == xs[p+k]
    float win[8];
#pragma unroll
    for (int i = 0; i < 8; i++) win[i] = xs[i];

    float v = 0.0f;

    // ---- warm-up: recurrence only ----
    for (int p = 0; p < nwarm; p += 8) {
#pragma unroll
        for (int u = 0; u < 8; u++) {
            float I = 0.0f;
#pragma unroll
            for (int k = 0; k < KK; k++) I = fmaf(w[k], win[(u + k) & 7], I);
            const float vpre = fmaf(oma, I, alpha * v);
            v = (vpre >= THR) ? 0.0f : vpre;
            win[u] = xs[p + u + 8];
        }
    }

    float* const outI = out;
    float* const outZ = out + (size_t)BB * FF * LL;
    float* const outS = out + (size_t)2 * BB * FF * LL;
    float* const logits = out + (size_t)3 * BB * FF * LL;

    const int swz = (f >> 1) & 3;             // staging swizzle for row f
    const int rdp = (f & 3) ^ ((f >> 3) & 3); // write-out physical slot (j-invariant)
    const int g4 = f >> 4;                    // logits group 0..3
    const int cc = f & 15;                    // logits time column 0..15
    const int gflip = g4 & 1;                 // odd groups: row order i^1

    // ---- main: TILE steps -> packed swizzled tiles -> coalesced write-out ----
    for (int jb = 0; jb < TT; jb += TILE) {
#pragma unroll
        for (int q = 0; q < TILE; q += 8) {
            float Ia[8], Za[8];
#pragma unroll
            for (int u = 0; u < 8; u++) {
                float I = 0.0f;
#pragma unroll
                for (int k = 0; k < KK; k++) I = fmaf(w[k], win[(u + k) & 7], I);
                const float vpre = fmaf(oma, I, alpha * v);
                Ia[u] = I;
                Za[u] = fmaf(BETA, vpre, -BETA * THR);
                v = (vpre >= THR) ? 0.0f : vpre;
                win[u] = xs[nwarm + jb + q + u + 8];
            }
            const int s0 = q >> 2;            // slot of first float4 (0 or 2)
            const int o0 = f * TILE + ((s0) ^ swz) * 4;
            const int o1 = f * TILE + ((s0 + 1) ^ swz) * 4;
            *(float4*)&tI[o0] = make_float4(Ia[0], Ia[1], Ia[2], Ia[3]);
            *(float4*)&tI[o1] = make_float4(Ia[4], Ia[5], Ia[6], Ia[7]);
            *(float4*)&tZ[o0] = make_float4(Za[0], Za[1], Za[2], Za[3]);
            *(float4*)&tZ[o1] = make_float4(Za[4], Za[5], Za[6], Za[7]);
        }
        __syncthreads();

        const int colbase = t0 + jb;

        // Coalesced write-out: 4 lanes cover one 64B row segment (full sectors).
#pragma unroll
        for (int j = 0; j < 4; j++) {
            const int row = j * 16 + (f >> 2);
            const int so = row * TILE + rdp * 4;
            const size_t g = (size_t)(b * FF + row) * LL + colbase + (f & 3) * 4;
            const float4 i4 = *(const float4*)&tI[so];
            const float4 z4 = *(const float4*)&tZ[so];
            float4 s4;
            s4.x = (z4.x >= 0.0f) ? 1.0f : 0.0f;
            s4.y = (z4.y >= 0.0f) ? 1.0f : 0.0f;
            s4.z = (z4.z >= 0.0f) ? 1.0f : 0.0f;
            s4.w = (z4.w >= 0.0f) ? 1.0f : 0.0f;
            *(float4*)&outI[g] = i4;
            *(float4*)&outZ[g] = z4;
            *(float4*)&outS[g] = s4;
        }

        // Logits partial max: group g4 reduces its 16 filters for column cc.
        // Odd groups traverse rows as i^1 -> half-warps hit disjoint bank halves.
        {
            const int ps = cc >> 2;    // logical slot of column cc
            const int pe = cc & 3;     // element within float4
            float m = -3.4e38f;
#pragma unroll
            for (int i = 0; i < 16; i++) {
                const int r = g4 * 16 + (i ^ gflip);
                m = fmaxf(m, tZ[r * TILE + ((ps ^ ((r >> 1) & 3)) << 2) + pe]);
            }
            pm[cc * 4 + g4] = m;
        }
        __syncthreads();

        // Combine 4 group-partials per column; 16 threads, 64B coalesced store.
        if (f < TILE) {
            const float4 p4 = *(const float4*)&pm[f * 4];
            logits[b * LL + colbase + f] =
                fmaxf(fmaxf(p4.x, p4.y), fmaxf(p4.z, p4.w));
        }
    }
}

extern "C" void kernel_launch(void* const* d_in, const int* in_sizes, int n_in,
                              void* d_out, int out_size)
{
    const float* x       = (const float*)d_in[0];
    const float* conv_w  = (const float*)d_in[1];
    const float* raw_tau = (const float*)d_in[2];
    float* out = (float*)d_out;

    dim3 grid(BB, NCH);
    snn_fused_kernel<<<grid, FF>>>(x, conv_w, raw_tau, out);
}

// round 13
// speedup vs baseline: 1.4425x; 1.4425x over previous
#include <cuda_runtime.h>

// Problem constants
#define BB 32
#define FF 64
#define LL 8192
#define KK 8
#define TT 128          // output steps per chunk
#define WW 128          // warm-up steps (validated rounds 2-11: rel_err ~8.7e-8)
#define NCH (LL / TT)   // 64 chunks -> 2048 blocks
#define TILE 32         // steps buffered in smem before coalesced write-out
#define TPAD 36         // row stride: conflict-free STS.128 / LDS.128 / logits
#define XS_N (WW + TT + KK)   // 264

#define X_SCALE 20.0f
#define THR 0.25f
#define BETA 15.0f

// Streaming (evict-first) 128-bit store: output is write-once, never re-read.
__device__ __forceinline__ void stg_cs(float* p, float4 v) {
    asm volatile("st.global.cs.v4.f32 [%0], {%1, %2, %3, %4};"
                 :: "l"(p), "f"(v.x), "f"(v.y), "f"(v.z), "f"(v.w) : "memory");
}

// Fused conv + LIF scan + logits. Grid (B, NCH), 64 threads (one per filter).
// Round-5 geometry (best measured): every 128B output line is written whole
// by one 8-lane store group; all smem patterns conflict-free.
// s derived from z at write-out (s = z>=0, z = BETA*(vpre-THR)).
__global__ __launch_bounds__(64, 11) void snn_fused_kernel(
    const float* __restrict__ x,
    const float* __restrict__ conv_w,
    const float* __restrict__ raw_tau,
    float* __restrict__ out)
{
    __shared__ float xs[XS_N];
    __shared__ float tI[FF * TPAD];
    __shared__ float tZ[FF * TPAD];
    __shared__ float pm[TILE * 2];    // per-column partial maxes (2 warps)

    const int b = blockIdx.x;
    const int c = blockIdx.y;
    const int f = threadIdx.x;
    const int t0 = c * TT;
    const int tstart = (c == 0) ? 0 : (t0 - WW);
    const int nwarm = t0 - tstart;    // 0 or WW

    // Unit-norm filter weights (clamp 1e-8)
    float w[KK];
    float nrm = 0.0f;
#pragma unroll
    for (int k = 0; k < KK; k++) {
        w[k] = conv_w[f * KK + k];
        nrm += w[k] * w[k];
    }
    nrm = fmaxf(sqrtf(nrm), 1e-8f);
#pragma unroll
    for (int k = 0; k < KK; k++) w[k] = w[k] / nrm;

    // alpha = exp(-1 / (softplus(raw_tau) + 1e-4))
    const float rt = raw_tau[f];
    const float sp = fmaxf(rt, 0.0f) + log1pf(expf(-fabsf(rt)));
    const float alpha = expf(-1.0f / (sp + 1e-4f));
    const float oma = 1.0f - alpha;

    // Stage pre-scaled x window, zero-padded left. xs[i] = 20*x[b, tstart-7+i]
    const float* xb = x + b * LL;
    const int base = tstart - (KK - 1);
    const int total = nwarm + TT + (KK - 1);
    for (int i = f; i < total; i += FF) {
        const int g = base + i;
        xs[i] = (g >= 0) ? (X_SCALE * xb[g]) : 0.0f;
    }
    __syncthreads();

    // 8-register circular window: win[(p+k)&7] == xs[p+k]
    float win[8];
#pragma unroll
    for (int i = 0; i < 8; i++) win[i] = xs[i];

    float v = 0.0f;

    // ---- warm-up: recurrence only ----
    for (int p = 0; p < nwarm; p += 8) {
#pragma unroll
        for (int u = 0; u < 8; u++) {
            float I = 0.0f;
#pragma unroll
            for (int k = 0; k < KK; k++) I = fmaf(w[k], win[(u + k) & 7], I);
            const float vpre = fmaf(oma, I, alpha * v);
            v = (vpre >= THR) ? 0.0f : vpre;
            win[u] = xs[p + u + 8];
        }
    }

    float* const outI = out;
    float* const outZ = out + (size_t)BB * FF * LL;
    float* const outS = out + (size_t)2 * BB * FF * LL;
    float* const logits = out + (size_t)3 * BB * FF * LL;

    const int g2 = f >> 5;        // warp id (filter group of 32)
    const int cc = f & 31;        // time column 0..31

    // ---- main: TILE steps -> smem tiles -> coalesced write-out ----
    for (int jb = 0; jb < TT; jb += TILE) {
#pragma unroll
        for (int q = 0; q < TILE; q += 8) {
            float Ia[8], Za[8];
#pragma unroll
            for (int u = 0; u < 8; u++) {
                float I = 0.0f;
#pragma unroll
                for (int k = 0; k < KK; k++) I = fmaf(w[k], win[(u + k) & 7], I);
                const float vpre = fmaf(oma, I, alpha * v);
                Ia[u] = I;
                Za[u] = fmaf(BETA, vpre, -BETA * THR);
                v = (vpre >= THR) ? 0.0f : vpre;
                win[u] = xs[nwarm + jb + q + u + 8];
            }
            const int off = f * TPAD + q;
            *(float4*)&tI[off]     = make_float4(Ia[0], Ia[1], Ia[2], Ia[3]);
            *(float4*)&tI[off + 4] = make_float4(Ia[4], Ia[5], Ia[6], Ia[7]);
            *(float4*)&tZ[off]     = make_float4(Za[0], Za[1], Za[2], Za[3]);
            *(float4*)&tZ[off + 4] = make_float4(Za[4], Za[5], Za[6], Za[7]);
        }
        __syncthreads();

        const int colbase = t0 + jb;

        // Coalesced write-out: 8 consecutive lanes cover one full 128B row line.
#pragma unroll
        for (int p2 = 0; p2 < 8; p2++) {
            const int idx = p2 * 256 + f * 4;   // linear in 64x32 tile
            const int row = idx >> 5;
            const int col = idx & 31;
            const size_t g = (size_t)(b * FF + row) * LL + colbase + col;
            const int so = row * TPAD + col;
            const float4 i4 = *(const float4*)&tI[so];
            const float4 z4 = *(const float4*)&tZ[so];
            float4 s4;
            s4.x = (z4.x >= 0.0f) ? 1.0f : 0.0f;
            s4.y = (z4.y >= 0.0f) ? 1.0f : 0.0f;
            s4.z = (z4.z >= 0.0f) ? 1.0f : 0.0f;
            s4.w = (z4.w >= 0.0f) ? 1.0f : 0.0f;
            stg_cs(&outI[g], i4);
            stg_cs(&outZ[g], z4);
            stg_cs(&outS[g], s4);
        }

        // Logits partial max: warp g2 reduces its 32 filters for column cc.
        {
            float m = -3.4e38f;
#pragma unroll
            for (int ff2 = 0; ff2 < 32; ff2++)
                m = fmaxf(m, tZ[(g2 * 32 + ff2) * TPAD + cc]);
            pm[cc * 2 + g2] = m;
        }
        __syncthreads();

        // Combine the 2 warp-partials per column; 32 threads, coalesced store.
        if (f < TILE) {
            logits[b * LL + colbase + f] = fmaxf(pm[f * 2], pm[f * 2 + 1]);
        }
    }
}

extern "C" void kernel_launch(void* const* d_in, const int* in_sizes, int n_in,
                              void* d_out, int out_size)
{
    const float* x       = (const float*)d_in[0];
    const float* conv_w  = (const float*)d_in[1];
    const float* raw_tau = (const float*)d_in[2];
    float* out = (float*)d_out;

    dim3 grid(BB, NCH);
    snn_fused_kernel<<<grid, FF>>>(x, conv_w, raw_tau, out);
}